// round 10
// baseline (speedup 1.0000x reference)
#include <cuda_runtime.h>
#include <cuda_bf16.h>

// feeds: [N=65536, D=512] f32, rep: [N] int32 in [0,8), out: [S=262144, D] f32.
// out row j = feeds[i] where cumsum(rep) first exceeds j; rows >= total are 0.
//
// Pipeline:
//   1) scan_kernel: 64 blocks x 1024, single-pass scan with decoupled
//      lookback (all 64 blocks co-resident on 148 SMs -> spin is safe).
//   2) scatter_kernel: N blocks scatter rows (row in regs, coalesced 2KB
//      __stcs stores); extra blocks zero the tail AND reset the lookback
//      flags for the next graph replay (stream-ordered after the scan).

#define MAX_N 65536
#define SCAN_BLOCKS 64
__device__ int g_cum[MAX_N];
__device__ volatile int g_bsum[SCAN_BLOCKS];
__device__ volatile int g_flag[SCAN_BLOCKS];   // zero-init; reset by scatter

__global__ void scan_kernel(const int* __restrict__ rep) {
    __shared__ int ws[32];
    __shared__ int s_off;
    const int tid = threadIdx.x;
    const int lane = tid & 31, wid = tid >> 5;
    const int b = blockIdx.x;

    // Warp-level inclusive scan of own item.
    const int idx = b * 1024 + tid;
    int x = __ldg(rep + idx);
    #pragma unroll
    for (int off = 1; off < 32; off <<= 1) {
        int y = __shfl_up_sync(0xffffffffu, x, off);
        if (lane >= off) x += y;
    }
    if (lane == 31) ws[wid] = x;
    __syncthreads();

    if (wid == 0) {
        // Cross-warp inclusive scan; lane 31 now holds the block aggregate.
        int w = ws[lane];
        #pragma unroll
        for (int off = 1; off < 32; off <<= 1) {
            int y = __shfl_up_sync(0xffffffffu, w, off);
            if (lane >= off) w += y;
        }
        ws[lane] = w;
        if (lane == 31) {            // publish aggregate ASAP
            g_bsum[b] = w;
            __threadfence();
            g_flag[b] = 1;
        }
        // Lookback: sum aggregates of blocks [0, b).
        int v = 0;
        if (lane < b) {
            while (g_flag[lane] == 0) {}
            v += g_bsum[lane];
        }
        if (lane + 32 < b) {
            while (g_flag[lane + 32] == 0) {}
            v += g_bsum[lane + 32];
        }
        #pragma unroll
        for (int off = 16; off > 0; off >>= 1)
            v += __shfl_down_sync(0xffffffffu, v, off);
        if (lane == 0) s_off = v;
    }
    __syncthreads();

    g_cum[idx] = x + (wid > 0 ? ws[wid - 1] : 0) + s_off;
}

// blocks [0, N): one per source row, 128 threads x float4 = one 2KB row.
// blocks [N, N+TAIL_BLOCKS): grid-stride zero of [total*d4, n4).
// Block N additionally resets the lookback flags for the next replay.
#define TAIL_BLOCKS 2048
__global__ void scatter_kernel(const float4* __restrict__ feeds,
                               const int* __restrict__ rep,
                               float4* __restrict__ out, int d4, int N,
                               size_t n4) {
    const int b = blockIdx.x;
    if (b < N) {
        const int r = rep[b];
        if (r == 0) return;
        const int start = g_cum[b] - r;
        const float4 v = feeds[(size_t)b * d4 + threadIdx.x];
        float4* dst = out + (size_t)start * d4 + threadIdx.x;
        for (int k = 0; k < r; k++)
            __stcs(dst + (size_t)k * d4, v);
    } else {
        if (b == N && threadIdx.x < SCAN_BLOCKS)
            g_flag[threadIdx.x] = 0;   // re-arm lookback for next replay
        const int total = g_cum[N - 1];
        const size_t begin = (size_t)total * d4;
        const size_t tb = b - N;
        const size_t stride = (size_t)TAIL_BLOCKS * blockDim.x;
        const float4 z = make_float4(0.f, 0.f, 0.f, 0.f);
        for (size_t i = begin + tb * blockDim.x + threadIdx.x; i < n4;
             i += stride)
            __stcs(out + i, z);
    }
}

extern "C" void kernel_launch(void* const* d_in, const int* in_sizes, int n_in,
                              void* d_out, int out_size) {
    const float4* feeds = (const float4*)d_in[0];
    const int*    rep   = (const int*)d_in[1];
    float4*       out   = (float4*)d_out;

    const int N = in_sizes[1];                 // 65536 source rows
    const int D = in_sizes[0] / N;             // 512
    const int d4 = D / 4;                      // 128 float4 per row
    const int S = out_size / D;                // 262144 output rows
    const size_t n4 = (size_t)S * d4;

    scan_kernel<<<SCAN_BLOCKS, 1024>>>(rep);
    scatter_kernel<<<N + TAIL_BLOCKS, d4>>>(feeds, rep, out, d4, N, n4);
}